// round 16
// baseline (speedup 1.0000x reference)
#include <cuda_runtime.h>
#include <cuda_fp16.h>
#include <math.h>

#define D 128
#define NMAX 50000
#define EMAX 800000

// Scratch (device globals — zero-initialized at load; k_scan23 re-zeroes
// g_cnt/g_degex each run so every invocation starts identically).
__device__ float g_xw[(size_t)NMAX * D];    // x @ W (fp32, self term)
__device__ uint2 g_xwh[(size_t)NMAX * 32];  // x @ W packed 4x fp16 per lane
__device__ float g_p1[NMAX];                // x . w_pred[:128]
__device__ float g_p2[NMAX];                // x . w_pred[128:]
__device__ float g_degex[NMAX];             // weighted in-degree EXCESS (deg-1)
__device__ int   g_cnt[NMAX];               // in-degree count (by tgt)
__device__ int   g_rowstart[NMAX + 1];      // CSR row offsets (by tgt)
__device__ int   g_cursor[NMAX];            // fill cursors
__device__ int2  g_pack[EMAX];              // (src, ew bits) grouped by tgt
__device__ int   g_bsum[256];               // block sums for scan
// W split-bf16 fragment table: [ks(8)][nt(16)][lane(32)] -> {bhi0,bhi1,blo0,blo1}
__device__ uint4 g_wfrag[8 * 16 * 32];

// Split a float2 into packed bf16 hi and bf16 residual lo (lo half = .x).
__device__ __forceinline__ void split2(float fx, float fy,
                                       unsigned& hi, unsigned& lo) {
    asm("cvt.rn.bf16x2.f32 %0, %1, %2;" : "=r"(hi) : "f"(fy), "f"(fx));
    float h0 = __uint_as_float(hi << 16);
    float h1 = __uint_as_float(hi & 0xffff0000u);
    float r0 = fx - h0, r1 = fy - h1;
    asm("cvt.rn.bf16x2.f32 %0, %1, %2;" : "=r"(lo) : "f"(r1), "f"(r0));
}

__device__ __forceinline__ void mma_bf16(float* c, const unsigned* a,
                                         unsigned b0, unsigned b1) {
    asm volatile(
        "mma.sync.aligned.m16n8k16.row.col.f32.bf16.bf16.f32 "
        "{%0,%1,%2,%3}, {%4,%5,%6,%7}, {%8,%9}, {%0,%1,%2,%3};"
        : "+f"(c[0]), "+f"(c[1]), "+f"(c[2]), "+f"(c[3])
        : "r"(a[0]), "r"(a[1]), "r"(a[2]), "r"(a[3]), "r"(b0), "r"(b1));
}

// ---------------------------------------------------------------------------
// K1 (fused): blocks [0, npre): per-node dots with w_pred halves.
//             blocks [npre, npre+ncntb): in-degree counts by target.
//             blocks [npre+ncntb, ...): build W split-bf16 fragment table.
// ---------------------------------------------------------------------------
__global__ void k_precnt(const float* __restrict__ x,
                         const float* __restrict__ wp,
                         const float* __restrict__ W,
                         const int* __restrict__ tgt,
                         int n, int e, int npre, int ncntb) {
    if ((int)blockIdx.x < npre) {
        int warp = (blockIdx.x * 256 + threadIdx.x) >> 5;
        int lane = threadIdx.x & 31;
        if (warp >= n) return;
        float4 xv = ((const float4*)(x + (size_t)warp * D))[lane];
        float4 w1 = ((const float4*)wp)[lane];
        float4 w2 = ((const float4*)(wp + D))[lane];
        float s1 = xv.x * w1.x + xv.y * w1.y + xv.z * w1.z + xv.w * w1.w;
        float s2 = xv.x * w2.x + xv.y * w2.y + xv.z * w2.z + xv.w * w2.w;
#pragma unroll
        for (int o = 16; o > 0; o >>= 1) {
            s1 += __shfl_xor_sync(0xffffffffu, s1, o);
            s2 += __shfl_xor_sync(0xffffffffu, s2, o);
        }
        if (lane == 0) {
            g_p1[warp] = s1;
            g_p2[warp] = s2;
        }
    } else if ((int)blockIdx.x < npre + ncntb) {
        int i = (blockIdx.x - npre) * 256 + threadIdx.x;
        if (i >= e) return;
        atomicAdd(&g_cnt[tgt[i]], 1);
    } else {
        // W fragment table: idx -> (ks, nt, lane)
        int idx = (blockIdx.x - npre - ncntb) * 256 + threadIdx.x;
        if (idx >= 8 * 16 * 32) return;
        int lane = idx & 31;
        int g = lane >> 2, t = lane & 3;
        int nt = (idx >> 5) & 15;
        int ks = idx >> 9;
        int nc = nt * 8 + g;
        int k0 = ks * 16 + 2 * t;
        float w00 = W[(k0 + 0) * D + nc];
        float w01 = W[(k0 + 1) * D + nc];
        float w10 = W[(k0 + 8) * D + nc];
        float w11 = W[(k0 + 9) * D + nc];
        unsigned h0, l0, h1, l1;
        split2(w00, w01, h0, l0);   // b0: k=2t (lo half), k=2t+1 (hi half)
        split2(w10, w11, h1, l1);   // b1: k=2t+8, 2t+9
        g_wfrag[idx] = make_uint4(h0, h1, l0, l1);
    }
}

// ---------------------------------------------------------------------------
// K2a: per-block exclusive scan of g_cnt; block sums -> g_bsum.
// ---------------------------------------------------------------------------
__global__ void k_scan1(int n) {
    __shared__ int sd[256];
    int tid = threadIdx.x;
    int i = blockIdx.x * 256 + tid;
    int v = (i < n) ? g_cnt[i] : 0;
    sd[tid] = v;
    __syncthreads();
#pragma unroll
    for (int off = 1; off < 256; off <<= 1) {
        int u = (tid >= off) ? sd[tid - off] : 0;
        __syncthreads();
        sd[tid] += u;
        __syncthreads();
    }
    if (i < n) g_rowstart[i] = sd[tid] - v;
    if (tid == 255) g_bsum[blockIdx.x] = sd[255];
}

// ---------------------------------------------------------------------------
// K2b (fused scan2+scan3+reset): every block redundantly scans g_bsum in
// smem, applies its offset, finalizes rowstart/cursor, re-zeroes cnt/degex.
// ---------------------------------------------------------------------------
__global__ void k_scan23(int n, int e, int nb) {
    __shared__ int sd[256];
    int tid = threadIdx.x;
    int v = (tid < nb) ? g_bsum[tid] : 0;
    sd[tid] = v;
    __syncthreads();
#pragma unroll
    for (int off = 1; off < 256; off <<= 1) {
        int u = (tid >= off) ? sd[tid - off] : 0;
        __syncthreads();
        sd[tid] += u;
        __syncthreads();
    }
    int boff = (blockIdx.x > 0) ? sd[blockIdx.x - 1] : 0;  // exclusive
    int i = blockIdx.x * 256 + tid;
    if (i < n) {
        int r = g_rowstart[i] + boff;
        g_rowstart[i] = r;
        g_cursor[i] = r;
        g_cnt[i] = 0;       // reset for next run
        g_degex[i] = 0.0f;  // reset for next run (written only downstream)
    }
    if (i == 0) g_rowstart[n] = e;
}

// ---------------------------------------------------------------------------
// K3 (fused): blocks [0, ngemm): TENSOR-CORE GEMM, TWO nt-HALVES per warp:
//   acc[8][4] (32 regs, was 64) with a full ks sweep per half; A fragments
//   re-loaded from L2-resident x per half (+25MB, trivial). launch_bounds
//   (256,3) -> 24 warps/SM (1.5x R15): hides wfrag/x latency AND gives the
//   edge blocks more resident warps.
// blocks [ngemm, ...): edge sigmoid + degex atomics + CSR fill.
// ---------------------------------------------------------------------------
__global__ void __launch_bounds__(256, 3)
k_gemmedge(const float* __restrict__ x,
           const int* __restrict__ src, const int* __restrict__ tgt,
           const float* __restrict__ bp, int n, int e, int ngemm) {
    if ((int)blockIdx.x >= ngemm) {
        int i = (blockIdx.x - ngemm) * 256 + threadIdx.x;
        if (i >= e) return;
        int s = src[i], t = tgt[i];
        float z = g_p1[s] + g_p2[t] + bp[0];
        float w = __fdividef(1.0f, 1.0f + __expf(-z));
        atomicAdd(&g_degex[t], w);
        int pos = atomicAdd(&g_cursor[t], 1);
        g_pack[pos] = make_int2(s, __float_as_int(w));
        return;
    }

    int tid = threadIdx.x;
    int warp = tid >> 5;
    int lane = tid & 31;
    int g = lane >> 2;       // row group 0..7
    int t = lane & 3;        // k/col group 0..3
    int rowg = blockIdx.x * 128 + warp * 16 + g;
    int rowg8 = rowg + 8;
    bool ok0 = rowg < n, ok1 = rowg8 < n;
    const float* xr0 = x + (size_t)rowg * D;
    const float* xr8 = x + (size_t)rowg8 * D;
    int q = t >> 1;

#pragma unroll 1
    for (int half = 0; half < 2; half++) {
        float acc[8][4];
#pragma unroll
        for (int nt = 0; nt < 8; nt++)
#pragma unroll
            for (int j = 0; j < 4; j++) acc[nt][j] = 0.f;

#pragma unroll 1
        for (int ks = 0; ks < 8; ks++) {
            int k0 = ks * 16 + 2 * t;
            float2 z2 = make_float2(0.f, 0.f);
            float2 f00 = ok0 ? *(const float2*)(xr0 + k0) : z2;
            float2 f10 = ok1 ? *(const float2*)(xr8 + k0) : z2;
            float2 f08 = ok0 ? *(const float2*)(xr0 + k0 + 8) : z2;
            float2 f18 = ok1 ? *(const float2*)(xr8 + k0 + 8) : z2;
            unsigned ahi[4], alo[4];
            split2(f00.x, f00.y, ahi[0], alo[0]);
            split2(f10.x, f10.y, ahi[1], alo[1]);
            split2(f08.x, f08.y, ahi[2], alo[2]);
            split2(f18.x, f18.y, ahi[3], alo[3]);
            const uint4* wrow = g_wfrag + (ks << 9) + (half << 8) + lane;
#pragma unroll
            for (int nt = 0; nt < 8; nt++) {
                uint4 wf = wrow[nt << 5];
                mma_bf16(acc[nt], ahi, wf.x, wf.y);  // hi*hi
                mma_bf16(acc[nt], ahi, wf.z, wf.w);  // hi*lo
                mma_bf16(acc[nt], alo, wf.x, wf.y);  // lo*hi
            }
        }

        // Epilogue for this half: cols (half*8+nt)*8 + ...
#pragma unroll
        for (int nt = 0; nt < 8; nt++) {
            int ntg = half * 8 + nt;
            float c0 = acc[nt][0], c1 = acc[nt][1];
            float c2 = acc[nt][2], c3 = acc[nt][3];
            if (ok0)
                *(float2*)&g_xw[(size_t)rowg * D + ntg * 8 + 2 * t] =
                    make_float2(c0, c1);
            if (ok1)
                *(float2*)&g_xw[(size_t)rowg8 * D + ntg * 8 + 2 * t] =
                    make_float2(c2, c3);
            __half2 hA = __floats2half2_rn(c0, c1);
            __half2 hB = __floats2half2_rn(c2, c3);
            unsigned uA = *(unsigned*)&hA;
            unsigned uB = *(unsigned*)&hB;
            unsigned uAo = __shfl_xor_sync(0xffffffffu, uA, 1);
            unsigned uBo = __shfl_xor_sync(0xffffffffu, uB, 1);
            if ((t & 1) == 0) {
                if (ok0)
                    g_xwh[(size_t)rowg * 32 + ntg * 2 + q] = make_uint2(uA, uAo);
                if (ok1)
                    g_xwh[(size_t)rowg8 * 32 + ntg * 2 + q] = make_uint2(uB, uBo);
            }
        }
    }
}

// ---------------------------------------------------------------------------
// K4: atomic-free aggregation, warp per TARGET node; __launch_bounds__(256,6)
// (R10-proven: regs<=40, 48 warps/SM). 4-way unrolled fp16 row gathers.
// ---------------------------------------------------------------------------
__global__ void __launch_bounds__(256, 6)
k_aggregate(const float* __restrict__ b, float* __restrict__ out, int n) {
    int t = (blockIdx.x * blockDim.x + threadIdx.x) >> 5;
    int lane = threadIdx.x & 31;
    if (t >= n) return;
    float dt = rsqrtf(1.0f + g_degex[t]);
    float4 xv = ((const float4*)g_xw)[(size_t)t * 32 + lane];
    float sc = dt * dt;
    float4 acc = make_float4(sc * xv.x, sc * xv.y, sc * xv.z, sc * xv.w);

    int p0 = g_rowstart[t];
    int cnt = g_rowstart[t + 1] - p0;

    for (int base = 0; base < cnt; base += 32) {
        int idx = base + lane;
        int s = 0;
        float c = 0.f;
        if (idx < cnt) {
            int2 pk = g_pack[p0 + idx];
            s = pk.x;
            c = __int_as_float(pk.y) * rsqrtf(1.0f + g_degex[s]) * dt;
        }
        int m = min(32, cnt - base);
        int j = 0;
        for (; j + 4 <= m; j += 4) {
            int s0 = __shfl_sync(0xffffffffu, s, j);
            int s1 = __shfl_sync(0xffffffffu, s, j + 1);
            int s2 = __shfl_sync(0xffffffffu, s, j + 2);
            int s3 = __shfl_sync(0xffffffffu, s, j + 3);
            float c0 = __shfl_sync(0xffffffffu, c, j);
            float c1 = __shfl_sync(0xffffffffu, c, j + 1);
            float c2 = __shfl_sync(0xffffffffu, c, j + 2);
            float c3 = __shfl_sync(0xffffffffu, c, j + 3);
            uint2 v0 = g_xwh[(size_t)s0 * 32 + lane];
            uint2 v1 = g_xwh[(size_t)s1 * 32 + lane];
            uint2 v2 = g_xwh[(size_t)s2 * 32 + lane];
            uint2 v3 = g_xwh[(size_t)s3 * 32 + lane];
            float2 a0 = __half22float2(*(__half2*)&v0.x);
            float2 d0 = __half22float2(*(__half2*)&v0.y);
            float2 a1 = __half22float2(*(__half2*)&v1.x);
            float2 d1 = __half22float2(*(__half2*)&v1.y);
            float2 a2 = __half22float2(*(__half2*)&v2.x);
            float2 d2 = __half22float2(*(__half2*)&v2.y);
            float2 a3 = __half22float2(*(__half2*)&v3.x);
            float2 d3 = __half22float2(*(__half2*)&v3.y);
            acc.x += c0 * a0.x + c1 * a1.x + c2 * a2.x + c3 * a3.x;
            acc.y += c0 * a0.y + c1 * a1.y + c2 * a2.y + c3 * a3.y;
            acc.z += c0 * d0.x + c1 * d1.x + c2 * d2.x + c3 * d3.x;
            acc.w += c0 * d0.y + c1 * d1.y + c2 * d2.y + c3 * d3.y;
        }
        for (; j < m; j++) {
            int sj = __shfl_sync(0xffffffffu, s, j);
            float cj = __shfl_sync(0xffffffffu, c, j);
            uint2 v = g_xwh[(size_t)sj * 32 + lane];
            float2 a = __half22float2(*(__half2*)&v.x);
            float2 d = __half22float2(*(__half2*)&v.y);
            acc.x += cj * a.x;
            acc.y += cj * a.y;
            acc.z += cj * d.x;
            acc.w += cj * d.y;
        }
    }

    float4 bv = ((const float4*)b)[lane];
    ((float4*)out)[(size_t)t * 32 + lane] =
        make_float4(acc.x + bv.x, acc.y + bv.y, acc.z + bv.z, acc.w + bv.w);
}

// ---------------------------------------------------------------------------
extern "C" void kernel_launch(void* const* d_in, const int* in_sizes, int n_in,
                              void* d_out, int out_size) {
    const float* x  = (const float*)d_in[0];
    const int*   ei = (const int*)d_in[1];
    const float* W  = (const float*)d_in[2];
    const float* b  = (const float*)d_in[3];
    const float* wp = (const float*)d_in[4];
    const float* bp = (const float*)d_in[5];
    float* out = (float*)d_out;

    int n = in_sizes[0] / D;
    int e = in_sizes[1] / 2;
    const int* src = ei;
    const int* tgt = ei + e;
    int nb = (n + 255) / 256;        // scan blocks (<=256)
    int npre = (n + 7) / 8;          // precompute blocks (8 warps each)
    int ncntb = (e + 255) / 256;     // cnt / edgefill blocks
    int nwf = (8 * 16 * 32 + 255) / 256;  // W fragment-table blocks (16)
    int ngemm = (n + 127) / 128;     // gemm blocks (128 rows each)

    k_precnt<<<npre + ncntb + nwf, 256>>>(x, wp, W, tgt, n, e, npre, ncntb);
    k_scan1<<<nb, 256>>>(n);
    k_scan23<<<nb, 256>>>(n, e, nb);
    k_gemmedge<<<ngemm + ncntb, 256>>>(x, src, tgt, bp, n, e, ngemm);
    k_aggregate<<<(n * 32 + 255) / 256, 256>>>(b, out, n);
}

// round 17
// speedup vs baseline: 1.0265x; 1.0265x over previous
#include <cuda_runtime.h>
#include <cuda_fp16.h>
#include <math.h>

#define D 128
#define NMAX 50000
#define EMAX 800000

// Scratch (device globals — zero-initialized at load; k_scan23 re-zeroes
// g_cnt/g_degex each run so every invocation starts identically).
__device__ float g_xw[(size_t)NMAX * D];    // x @ W (fp32, self term)
__device__ uint2 g_xwh[(size_t)NMAX * 32];  // x @ W packed 4x fp16 per lane
__device__ float g_p1[NMAX];                // x . w_pred[:128]
__device__ float g_p2[NMAX];                // x . w_pred[128:]
__device__ float g_degex[NMAX];             // weighted in-degree EXCESS (deg-1)
__device__ int   g_cnt[NMAX];               // in-degree count (by tgt)
__device__ int   g_rowstart[NMAX + 1];      // CSR row offsets (by tgt)
__device__ int   g_cursor[NMAX];            // fill cursors
__device__ int2  g_pack[EMAX];              // (src, ew bits) grouped by tgt
__device__ int   g_bsum[256];               // block sums for scan
// W split-bf16 fragment table: [ks(8)][nt(16)][lane(32)] -> {bhi0,bhi1,blo0,blo1}
__device__ uint4 g_wfrag[8 * 16 * 32];

// Split a float2 into packed bf16 hi and bf16 residual lo (lo half = .x).
__device__ __forceinline__ void split2(float fx, float fy,
                                       unsigned& hi, unsigned& lo) {
    asm("cvt.rn.bf16x2.f32 %0, %1, %2;" : "=r"(hi) : "f"(fy), "f"(fx));
    float h0 = __uint_as_float(hi << 16);
    float h1 = __uint_as_float(hi & 0xffff0000u);
    float r0 = fx - h0, r1 = fy - h1;
    asm("cvt.rn.bf16x2.f32 %0, %1, %2;" : "=r"(lo) : "f"(r1), "f"(r0));
}

__device__ __forceinline__ void mma_bf16(float* c, const unsigned* a,
                                         unsigned b0, unsigned b1) {
    asm volatile(
        "mma.sync.aligned.m16n8k16.row.col.f32.bf16.bf16.f32 "
        "{%0,%1,%2,%3}, {%4,%5,%6,%7}, {%8,%9}, {%0,%1,%2,%3};"
        : "+f"(c[0]), "+f"(c[1]), "+f"(c[2]), "+f"(c[3])
        : "r"(a[0]), "r"(a[1]), "r"(a[2]), "r"(a[3]), "r"(b0), "r"(b1));
}

// ---------------------------------------------------------------------------
// K1 (fused): blocks [0, npre): per-node dots with w_pred halves.
//             blocks [npre, npre+ncntb): in-degree counts by target.
//             blocks [npre+ncntb, ...): build W split-bf16 fragment table.
// ---------------------------------------------------------------------------
__global__ void k_precnt(const float* __restrict__ x,
                         const float* __restrict__ wp,
                         const float* __restrict__ W,
                         const int* __restrict__ tgt,
                         int n, int e, int npre, int ncntb) {
    if ((int)blockIdx.x < npre) {
        int warp = (blockIdx.x * 256 + threadIdx.x) >> 5;
        int lane = threadIdx.x & 31;
        if (warp >= n) return;
        float4 xv = ((const float4*)(x + (size_t)warp * D))[lane];
        float4 w1 = ((const float4*)wp)[lane];
        float4 w2 = ((const float4*)(wp + D))[lane];
        float s1 = xv.x * w1.x + xv.y * w1.y + xv.z * w1.z + xv.w * w1.w;
        float s2 = xv.x * w2.x + xv.y * w2.y + xv.z * w2.z + xv.w * w2.w;
#pragma unroll
        for (int o = 16; o > 0; o >>= 1) {
            s1 += __shfl_xor_sync(0xffffffffu, s1, o);
            s2 += __shfl_xor_sync(0xffffffffu, s2, o);
        }
        if (lane == 0) {
            g_p1[warp] = s1;
            g_p2[warp] = s2;
        }
    } else if ((int)blockIdx.x < npre + ncntb) {
        int i = (blockIdx.x - npre) * 256 + threadIdx.x;
        if (i >= e) return;
        atomicAdd(&g_cnt[tgt[i]], 1);
    } else {
        // W fragment table: idx -> (ks, nt, lane)
        int idx = (blockIdx.x - npre - ncntb) * 256 + threadIdx.x;
        if (idx >= 8 * 16 * 32) return;
        int lane = idx & 31;
        int g = lane >> 2, t = lane & 3;
        int nt = (idx >> 5) & 15;
        int ks = idx >> 9;
        int nc = nt * 8 + g;
        int k0 = ks * 16 + 2 * t;
        float w00 = W[(k0 + 0) * D + nc];
        float w01 = W[(k0 + 1) * D + nc];
        float w10 = W[(k0 + 8) * D + nc];
        float w11 = W[(k0 + 9) * D + nc];
        unsigned h0, l0, h1, l1;
        split2(w00, w01, h0, l0);   // b0: k=2t (lo half), k=2t+1 (hi half)
        split2(w10, w11, h1, l1);   // b1: k=2t+8, 2t+9
        g_wfrag[idx] = make_uint4(h0, h1, l0, l1);
    }
}

// ---------------------------------------------------------------------------
// K2a: per-block exclusive scan of g_cnt; block sums -> g_bsum.
// ---------------------------------------------------------------------------
__global__ void k_scan1(int n) {
    __shared__ int sd[256];
    int tid = threadIdx.x;
    int i = blockIdx.x * 256 + tid;
    int v = (i < n) ? g_cnt[i] : 0;
    sd[tid] = v;
    __syncthreads();
#pragma unroll
    for (int off = 1; off < 256; off <<= 1) {
        int u = (tid >= off) ? sd[tid - off] : 0;
        __syncthreads();
        sd[tid] += u;
        __syncthreads();
    }
    if (i < n) g_rowstart[i] = sd[tid] - v;
    if (tid == 255) g_bsum[blockIdx.x] = sd[255];
}

// ---------------------------------------------------------------------------
// K2b (fused scan2+scan3+reset): every block redundantly scans g_bsum in
// smem, applies its offset, finalizes rowstart/cursor, re-zeroes cnt/degex.
// ---------------------------------------------------------------------------
__global__ void k_scan23(int n, int e, int nb) {
    __shared__ int sd[256];
    int tid = threadIdx.x;
    int v = (tid < nb) ? g_bsum[tid] : 0;
    sd[tid] = v;
    __syncthreads();
#pragma unroll
    for (int off = 1; off < 256; off <<= 1) {
        int u = (tid >= off) ? sd[tid - off] : 0;
        __syncthreads();
        sd[tid] += u;
        __syncthreads();
    }
    int boff = (blockIdx.x > 0) ? sd[blockIdx.x - 1] : 0;  // exclusive
    int i = blockIdx.x * 256 + tid;
    if (i < n) {
        int r = g_rowstart[i] + boff;
        g_rowstart[i] = r;
        g_cursor[i] = r;
        g_cnt[i] = 0;       // reset for next run
        g_degex[i] = 0.0f;  // reset for next run (written only downstream)
    }
    if (i == 0) g_rowstart[n] = e;
}

// ---------------------------------------------------------------------------
// K3 (fused): blocks [0, ngemm): TENSOR-CORE GEMM, COLUMN-SPLIT warps:
//   block = 64 rows x 128 cols; warp w = (rowgroup w>>1, colhalf w&1);
//   acc[8][4] (32 regs, ~70 total) + full single ks sweep per warp. The
//   sibling col-half warp re-reads the same x rows IN PARALLEL (same SM ->
//   L1 hit), unlike R16's serial re-read. 782 gemm blocks (2x parallelism),
//   launch_bounds(256,3) -> 24 warps/SM for BOTH gemm and edge blocks.
// blocks [ngemm, ...): edge sigmoid + degex atomics + CSR fill.
// ---------------------------------------------------------------------------
__global__ void __launch_bounds__(256, 3)
k_gemmedge(const float* __restrict__ x,
           const int* __restrict__ src, const int* __restrict__ tgt,
           const float* __restrict__ bp, int n, int e, int ngemm) {
    if ((int)blockIdx.x >= ngemm) {
        int i = (blockIdx.x - ngemm) * 256 + threadIdx.x;
        if (i >= e) return;
        int s = src[i], t = tgt[i];
        float z = g_p1[s] + g_p2[t] + bp[0];
        float w = __fdividef(1.0f, 1.0f + __expf(-z));
        atomicAdd(&g_degex[t], w);
        int pos = atomicAdd(&g_cursor[t], 1);
        g_pack[pos] = make_int2(s, __float_as_int(w));
        return;
    }

    int tid = threadIdx.x;
    int warp = tid >> 5;
    int lane = tid & 31;
    int rowgrp = warp >> 1;    // 0..3
    int colhalf = warp & 1;    // 0..1
    int g = lane >> 2;         // row group 0..7
    int t = lane & 3;          // k/col group 0..3
    int rowg = blockIdx.x * 64 + rowgrp * 16 + g;
    int rowg8 = rowg + 8;
    bool ok0 = rowg < n, ok1 = rowg8 < n;
    const float* xr0 = x + (size_t)rowg * D;
    const float* xr8 = x + (size_t)rowg8 * D;
    int q = t >> 1;

    float acc[8][4];
#pragma unroll
    for (int nt = 0; nt < 8; nt++)
#pragma unroll
        for (int j = 0; j < 4; j++) acc[nt][j] = 0.f;

#pragma unroll 1
    for (int ks = 0; ks < 8; ks++) {
        int k0 = ks * 16 + 2 * t;
        float2 z2 = make_float2(0.f, 0.f);
        float2 f00 = ok0 ? *(const float2*)(xr0 + k0) : z2;
        float2 f10 = ok1 ? *(const float2*)(xr8 + k0) : z2;
        float2 f08 = ok0 ? *(const float2*)(xr0 + k0 + 8) : z2;
        float2 f18 = ok1 ? *(const float2*)(xr8 + k0 + 8) : z2;
        unsigned ahi[4], alo[4];
        split2(f00.x, f00.y, ahi[0], alo[0]);
        split2(f10.x, f10.y, ahi[1], alo[1]);
        split2(f08.x, f08.y, ahi[2], alo[2]);
        split2(f18.x, f18.y, ahi[3], alo[3]);
        const uint4* wrow = g_wfrag + (ks << 9) + (colhalf << 8) + lane;
#pragma unroll
        for (int nt = 0; nt < 8; nt++) {
            uint4 wf = wrow[nt << 5];
            mma_bf16(acc[nt], ahi, wf.x, wf.y);  // hi*hi
            mma_bf16(acc[nt], ahi, wf.z, wf.w);  // hi*lo
            mma_bf16(acc[nt], alo, wf.x, wf.y);  // lo*hi
        }
    }

    // Epilogue: cols (colhalf*8+nt)*8 + ...
#pragma unroll
    for (int nt = 0; nt < 8; nt++) {
        int ntg = colhalf * 8 + nt;
        float c0 = acc[nt][0], c1 = acc[nt][1];
        float c2 = acc[nt][2], c3 = acc[nt][3];
        if (ok0)
            *(float2*)&g_xw[(size_t)rowg * D + ntg * 8 + 2 * t] =
                make_float2(c0, c1);
        if (ok1)
            *(float2*)&g_xw[(size_t)rowg8 * D + ntg * 8 + 2 * t] =
                make_float2(c2, c3);
        __half2 hA = __floats2half2_rn(c0, c1);
        __half2 hB = __floats2half2_rn(c2, c3);
        unsigned uA = *(unsigned*)&hA;
        unsigned uB = *(unsigned*)&hB;
        unsigned uAo = __shfl_xor_sync(0xffffffffu, uA, 1);
        unsigned uBo = __shfl_xor_sync(0xffffffffu, uB, 1);
        if ((t & 1) == 0) {
            if (ok0)
                g_xwh[(size_t)rowg * 32 + ntg * 2 + q] = make_uint2(uA, uAo);
            if (ok1)
                g_xwh[(size_t)rowg8 * 32 + ntg * 2 + q] = make_uint2(uB, uBo);
        }
    }
}

// ---------------------------------------------------------------------------
// K4: atomic-free aggregation, warp per TARGET node; __launch_bounds__(256,6)
// (R10-proven: regs<=40, 48 warps/SM). 4-way unrolled fp16 row gathers.
// ---------------------------------------------------------------------------
__global__ void __launch_bounds__(256, 6)
k_aggregate(const float* __restrict__ b, float* __restrict__ out, int n) {
    int t = (blockIdx.x * blockDim.x + threadIdx.x) >> 5;
    int lane = threadIdx.x & 31;
    if (t >= n) return;
    float dt = rsqrtf(1.0f + g_degex[t]);
    float4 xv = ((const float4*)g_xw)[(size_t)t * 32 + lane];
    float sc = dt * dt;
    float4 acc = make_float4(sc * xv.x, sc * xv.y, sc * xv.z, sc * xv.w);

    int p0 = g_rowstart[t];
    int cnt = g_rowstart[t + 1] - p0;

    for (int base = 0; base < cnt; base += 32) {
        int idx = base + lane;
        int s = 0;
        float c = 0.f;
        if (idx < cnt) {
            int2 pk = g_pack[p0 + idx];
            s = pk.x;
            c = __int_as_float(pk.y) * rsqrtf(1.0f + g_degex[s]) * dt;
        }
        int m = min(32, cnt - base);
        int j = 0;
        for (; j + 4 <= m; j += 4) {
            int s0 = __shfl_sync(0xffffffffu, s, j);
            int s1 = __shfl_sync(0xffffffffu, s, j + 1);
            int s2 = __shfl_sync(0xffffffffu, s, j + 2);
            int s3 = __shfl_sync(0xffffffffu, s, j + 3);
            float c0 = __shfl_sync(0xffffffffu, c, j);
            float c1 = __shfl_sync(0xffffffffu, c, j + 1);
            float c2 = __shfl_sync(0xffffffffu, c, j + 2);
            float c3 = __shfl_sync(0xffffffffu, c, j + 3);
            uint2 v0 = g_xwh[(size_t)s0 * 32 + lane];
            uint2 v1 = g_xwh[(size_t)s1 * 32 + lane];
            uint2 v2 = g_xwh[(size_t)s2 * 32 + lane];
            uint2 v3 = g_xwh[(size_t)s3 * 32 + lane];
            float2 a0 = __half22float2(*(__half2*)&v0.x);
            float2 d0 = __half22float2(*(__half2*)&v0.y);
            float2 a1 = __half22float2(*(__half2*)&v1.x);
            float2 d1 = __half22float2(*(__half2*)&v1.y);
            float2 a2 = __half22float2(*(__half2*)&v2.x);
            float2 d2 = __half22float2(*(__half2*)&v2.y);
            float2 a3 = __half22float2(*(__half2*)&v3.x);
            float2 d3 = __half22float2(*(__half2*)&v3.y);
            acc.x += c0 * a0.x + c1 * a1.x + c2 * a2.x + c3 * a3.x;
            acc.y += c0 * a0.y + c1 * a1.y + c2 * a2.y + c3 * a3.y;
            acc.z += c0 * d0.x + c1 * d1.x + c2 * d2.x + c3 * d3.x;
            acc.w += c0 * d0.y + c1 * d1.y + c2 * d2.y + c3 * d3.y;
        }
        for (; j < m; j++) {
            int sj = __shfl_sync(0xffffffffu, s, j);
            float cj = __shfl_sync(0xffffffffu, c, j);
            uint2 v = g_xwh[(size_t)sj * 32 + lane];
            float2 a = __half22float2(*(__half2*)&v.x);
            float2 d = __half22float2(*(__half2*)&v.y);
            acc.x += cj * a.x;
            acc.y += cj * a.y;
            acc.z += cj * d.x;
            acc.w += cj * d.y;
        }
    }

    float4 bv = ((const float4*)b)[lane];
    ((float4*)out)[(size_t)t * 32 + lane] =
        make_float4(acc.x + bv.x, acc.y + bv.y, acc.z + bv.z, acc.w + bv.w);
}

// ---------------------------------------------------------------------------
extern "C" void kernel_launch(void* const* d_in, const int* in_sizes, int n_in,
                              void* d_out, int out_size) {
    const float* x  = (const float*)d_in[0];
    const int*   ei = (const int*)d_in[1];
    const float* W  = (const float*)d_in[2];
    const float* b  = (const float*)d_in[3];
    const float* wp = (const float*)d_in[4];
    const float* bp = (const float*)d_in[5];
    float* out = (float*)d_out;

    int n = in_sizes[0] / D;
    int e = in_sizes[1] / 2;
    const int* src = ei;
    const int* tgt = ei + e;
    int nb = (n + 255) / 256;        // scan blocks (<=256)
    int npre = (n + 7) / 8;          // precompute blocks (8 warps each)
    int ncntb = (e + 255) / 256;     // cnt / edgefill blocks
    int nwf = (8 * 16 * 32 + 255) / 256;  // W fragment-table blocks (16)
    int ngemm = (n + 63) / 64;       // gemm blocks (64 rows each)

    k_precnt<<<npre + ncntb + nwf, 256>>>(x, wp, W, tgt, n, e, npre, ncntb);
    k_scan1<<<nb, 256>>>(n);
    k_scan23<<<nb, 256>>>(n, e, nb);
    k_gemmedge<<<ngemm + ncntb, 256>>>(x, src, tgt, bp, n, e, ngemm);
    k_aggregate<<<(n * 32 + 255) / 256, 256>>>(b, out, n);
}